// round 11
// baseline (speedup 1.0000x reference)
#include <cuda_runtime.h>
#include <cuda_pipeline.h>
#include <cstdint>

// libdevice precise expf (what XLA lowers jnp.exp(f32) to), immune to fast-math.
extern "C" __device__ float __nv_expf(float);

typedef unsigned long long ull;

// ---------------- problem constants ----------------
#define N_IMG 8
#define N_ANCH 250000
#define N_ANCH4 62500
#define K_PRE 2000
#define K_POST 1000
#define CAND_CAP 4096
#define NMS_THRESH 0.7f
#define XFORM_CLIP 4.135166556742356f
#define XMAX 1332.0f
#define YMAX 799.0f
#define NEG_BIG -1e9f
#define NBINS 4096
#define NB2 1024            // refined bins (512 in-bin + overflow)

// ---------------- device scratch (zero-init at load; self-cleaning per replay) ----------------
__device__ unsigned int g_hist[N_IMG * NBINS];
__device__ unsigned int g_hist2[N_IMG * NB2];
__device__ unsigned int g_done[N_IMG];
__device__ unsigned int g_done3[N_IMG];
__device__ unsigned int g_state[N_IMG * 4];      // [0]=coarse threshold key, [2]=cand_cnt
__device__ ull    g_cand[N_IMG * CAND_CAP];
__device__ float4 g_props4[N_IMG * K_PRE];
__device__ float  g_area[N_IMG * K_PRE];
__device__ float  g_scores[N_IMG * K_PRE];
__device__ unsigned char g_valid[N_IMG * K_PRE];
__device__ ull    g_mask[N_IMG * 2048 * 32];

__device__ __forceinline__ unsigned int okey_of(float f) {
    unsigned int b = __float_as_uint(f);
    return b ^ ((b & 0x80000000u) ? 0xFFFFFFFFu : 0x80000000u);
}

// ---------------- histogram (12-bit bins) + fused last-block threshold scan ----------------
__global__ void hist_kernel(const float4* __restrict__ obj4) {
    int img = blockIdx.y, t = threadIdx.x;
    __shared__ unsigned int sh[2][NBINS];
    __shared__ unsigned int s_ticket;
    __shared__ unsigned int wsums[8];
    for (int i = t; i < 2 * NBINS; i += 256) ((unsigned int*)sh)[i] = 0u;
    __syncthreads();
    const float4* o = obj4 + (size_t)img * N_ANCH4;
    int base = blockIdx.x * 2048 + t;
    float4 v[8]; bool m[8];
    #pragma unroll
    for (int u = 0; u < 8; u++) {
        int i = base + u * 256;
        m[u] = (i < N_ANCH4);
        v[u] = m[u] ? o[i] : make_float4(0.f, 0.f, 0.f, 0.f);
    }
    int p = (t >> 5) & 1;
    #pragma unroll
    for (int u = 0; u < 8; u++) if (m[u]) {
        atomicAdd(&sh[p][okey_of(v[u].x) >> 20], 1u);
        atomicAdd(&sh[p][okey_of(v[u].y) >> 20], 1u);
        atomicAdd(&sh[p][okey_of(v[u].z) >> 20], 1u);
        atomicAdd(&sh[p][okey_of(v[u].w) >> 20], 1u);
    }
    __syncthreads();
    for (int i = t; i < NBINS; i += 256) {
        unsigned int s = sh[0][i] + sh[1][i];
        if (s) atomicAdd(&g_hist[img * NBINS + i], s);
    }
    // ---- last-block coarse threshold scan (fence + ticket) ----
    __threadfence();
    __syncthreads();
    if (t == 0) s_ticket = atomicAdd(&g_done[img], 1u);
    __syncthreads();
    if (s_ticket == gridDim.x - 1) {
        int lane = t & 31, wid = t >> 5;
        int r0 = t * 16;                     // descending positions; bin = 4095 - r
        unsigned int cc[16], s[16];
        #pragma unroll
        for (int u = 0; u < 16; u++)
            cc[u] = __ldcg(&g_hist[img * NBINS + (NBINS - 1 - (r0 + u))]);
        unsigned int run = 0;
        #pragma unroll
        for (int u = 0; u < 16; u++) { run += cc[u]; s[u] = run; }
        unsigned int vv = run;
        #pragma unroll
        for (int off = 1; off < 32; off <<= 1) {
            unsigned int n = __shfl_up_sync(0xFFFFFFFFu, vv, off);
            if (lane >= off) vv += n;
        }
        if (lane == 31) wsums[wid] = vv;
        __syncthreads();
        if (wid == 0 && lane < 8) {
            unsigned int w = wsums[lane];
            #pragma unroll
            for (int off = 1; off < 8; off <<= 1) {
                unsigned int n = __shfl_up_sync(0xFFu, w, off);
                if ((int)lane >= off) w += n;
            }
            wsums[lane] = w;
        }
        __syncthreads();
        unsigned int excl = (wid > 0 ? wsums[wid - 1] : 0u) + (vv - run);
        if (excl < K_PRE && excl + run >= K_PRE) {
            int u = 0;
            #pragma unroll
            for (int q = 15; q >= 0; q--) if (excl + s[q] >= K_PRE) u = q;
            g_state[img * 4 + 0] = (unsigned int)(NBINS - 1 - (r0 + u)) << 20;
        }
        #pragma unroll
        for (int u = 0; u < 16; u++)
            g_hist[img * NBINS + (NBINS - 1 - (r0 + u))] = 0u;
        if (t == 0) g_done[img] = 0u;
    }
}

// ---------------- compact candidates + refined 21-bit histogram ----------------
__global__ void compact_kernel(const float4* __restrict__ obj4) {
    int img = blockIdx.y, t = threadIdx.x;
    __shared__ unsigned int h2[NB2];
    #pragma unroll
    for (int u = 0; u < 4; u++) h2[t + u * 256] = 0u;
    __syncthreads();
    unsigned int T = g_state[img * 4 + 0];
    unsigned int T11 = T >> 11;
    const float4* o = obj4 + (size_t)img * N_ANCH4;
    int base = blockIdx.x * 2048 + t;
    float4 v[8]; bool m[8];
    #pragma unroll
    for (int u = 0; u < 8; u++) {
        int i = base + u * 256;
        m[u] = (i < N_ANCH4);
        v[u] = m[u] ? o[i] : make_float4(0.f, 0.f, 0.f, 0.f);
    }
    #pragma unroll
    for (int u = 0; u < 8; u++) if (m[u]) {
        int i = base + u * 256;
        #pragma unroll
        for (int c = 0; c < 4; c++) {
            float f = (c == 0) ? v[u].x : (c == 1) ? v[u].y : (c == 2) ? v[u].z : v[u].w;
            unsigned int k = okey_of(f);
            if (k >= T) {
                unsigned int d = (k >> 11) - T11; if (d > NB2 - 1) d = NB2 - 1;
                atomicAdd(&h2[d], 1u);
                unsigned int pos = atomicAdd(&g_state[img * 4 + 2], 1u);
                if (pos < CAND_CAP)
                    g_cand[img * CAND_CAP + pos] =
                        ((ull)k << 32) | (unsigned int)(~(unsigned int)(4 * i + c));
            }
        }
    }
    __syncthreads();
    #pragma unroll
    for (int u = 0; u < 4; u++) {
        unsigned int s = h2[t + u * 256];
        if (s) atomicAdd(&g_hist2[img * NB2 + t + u * 256], s);
    }
}

// ---------------- sortdec: refined select + V=2 bitonic + decode ----------------
__device__ __forceinline__ void cas_reg(ull& a, ull& b, bool desc) {
    if ((a < b) == desc) { ull tmp = a; a = b; b = tmp; }
}

__global__ void sortdec_kernel(const float* __restrict__ anchors,
                               const float* __restrict__ deltas) {
    int img = blockIdx.x, t = threadIdx.x;   // 1024 threads
    __shared__ ull sh[CAND_CAP];             // 32 KB
    __shared__ unsigned int wsums[32];
    __shared__ int sT2;
    __shared__ int c2cnt;
    int w = t >> 5, lane = t & 31;
    unsigned int cnt = g_state[img * 4 + 2];
    if (cnt > CAND_CAP) cnt = CAND_CAP;
    if (t == 0) c2cnt = 0;
    ull v[4];
    #pragma unroll
    for (int u = 0; u < 4; u++) {
        int i = t + u * 1024;
        v[u] = (i < (int)cnt) ? g_cand[img * CAND_CAP + i] : 0ull;
    }
    unsigned int c = __ldcg(&g_hist2[img * NB2 + (NB2 - 1 - t)]);
    g_hist2[img * NB2 + (NB2 - 1 - t)] = 0u;   // self-clean for next replay
    unsigned int vv = c;
    #pragma unroll
    for (int off = 1; off < 32; off <<= 1) {
        unsigned int n = __shfl_up_sync(0xFFFFFFFFu, vv, off);
        if (lane >= off) vv += n;
    }
    if (lane == 31) wsums[w] = vv;
    __syncthreads();
    if (w == 0) {
        unsigned int x = wsums[lane];
        #pragma unroll
        for (int off = 1; off < 32; off <<= 1) {
            unsigned int n = __shfl_up_sync(0xFFFFFFFFu, x, off);
            if (lane >= off) x += n;
        }
        wsums[lane] = x;
    }
    __syncthreads();
    unsigned int excl = (w > 0 ? wsums[w - 1] : 0u) + (vv - c);
    if (excl < K_PRE && excl + c >= K_PRE) sT2 = NB2 - 1 - t;
    __syncthreads();
    unsigned int T11 = g_state[img * 4 + 0] >> 11;
    unsigned int dstar = (unsigned int)sT2;
    #pragma unroll
    for (int u = 0; u < 4; u++) {
        int i = t + u * 1024;
        unsigned int k = (unsigned int)(v[u] >> 32);
        unsigned int d = (k >> 11) - T11; if (d > NB2 - 1) d = NB2 - 1;
        bool p = (i < (int)cnt) && (d >= dstar);
        unsigned int ball = __ballot_sync(0xFFFFFFFFu, p);
        int bpos = 0;
        if (lane == 0 && ball) bpos = atomicAdd(&c2cnt, __popc(ball));
        bpos = __shfl_sync(0xFFFFFFFFu, bpos, 0);
        if (p) sh[bpos + __popc(ball & ((1u << lane) - 1u))] = v[u];
    }
    __syncthreads();
    int C2 = c2cnt;
    if (C2 <= 2048) {
        for (int i = t; i < 2048; i += 1024) if (i >= C2) sh[i] = 0ull;
        __syncthreads();
        ull r[2];
        #pragma unroll
        for (int e = 0; e < 2; e++) r[e] = sh[(w << 6) | (e << 5) | lane];
        for (int k = 2; k <= 2048; k <<= 1) {
            if (k >= 128) {
                #pragma unroll
                for (int e = 0; e < 2; e++) sh[(w << 6) | (e << 5) | lane] = r[e];
                __syncthreads();
                for (int j = k >> 1; j >= 64; j >>= 1) {
                    int i = ((t & ~(j - 1)) << 1) | (t & (j - 1));
                    int ixj = i | j;
                    bool desc = ((i & k) == 0);
                    ull A = sh[i], B = sh[ixj];
                    if ((A < B) == desc) { sh[i] = B; sh[ixj] = A; }
                    __syncthreads();
                }
                #pragma unroll
                for (int e = 0; e < 2; e++) r[e] = sh[(w << 6) | (e << 5) | lane];
            }
            if (k >= 64) {
                bool d = (((w << 6) & k) == 0);
                cas_reg(r[0], r[1], d);
            }
            int jmax = (k >> 1) < 16 ? (k >> 1) : 16;
            for (int j = jmax; j >= 1; j >>= 1) {
                #pragma unroll
                for (int e = 0; e < 2; e++) {
                    int i = (w << 6) | (e << 5) | lane;
                    bool desc = ((i & k) == 0);
                    bool iLow = ((lane & j) == 0);
                    ull p2 = __shfl_xor_sync(0xFFFFFFFFu, r[e], j);
                    ull mx = (r[e] > p2) ? r[e] : p2;
                    ull mn = (r[e] > p2) ? p2 : r[e];
                    r[e] = (iLow == desc) ? mx : mn;
                }
            }
        }
        #pragma unroll
        for (int e = 0; e < 2; e++) sh[(w << 6) | (e << 5) | lane] = r[e];
        __syncthreads();
    } else {
        for (int i = t; i < CAND_CAP; i += 1024)
            sh[i] = (i < (int)cnt) ? g_cand[img * CAND_CAP + i] : 0ull;
        __syncthreads();
        for (int k = 2; k <= CAND_CAP; k <<= 1) {
            for (int j = k >> 1; j > 0; j >>= 1) {
                for (int i = t; i < CAND_CAP; i += 1024) {
                    int ixj = i ^ j;
                    if (ixj > i) {
                        bool desc = ((i & k) == 0);
                        ull A = sh[i], B = sh[ixj];
                        if (desc ? (A < B) : (A > B)) { sh[i] = B; sh[ixj] = A; }
                    }
                }
                __syncthreads();
            }
        }
    }
    for (int r2 = t; r2 < K_PRE; r2 += 1024) {
        ull e = sh[r2];
        int idx = (int)(~(unsigned int)(e & 0xFFFFFFFFull));
        unsigned int kk = (unsigned int)(e >> 32);
        float score = __uint_as_float((kk & 0x80000000u) ? (kk ^ 0x80000000u) : ~kk);
        const float4 A = ((const float4*)anchors)[idx];
        const float4 D = ((const float4*)deltas)[(size_t)img * N_ANCH + idx];
        float w_  = __fadd_rn(__fsub_rn(A.z, A.x), 1.0f);
        float h_  = __fadd_rn(__fsub_rn(A.w, A.y), 1.0f);
        float cx = __fadd_rn(A.x, __fmul_rn(0.5f, w_));
        float cy = __fadd_rn(A.y, __fmul_rn(0.5f, h_));
        float dw = fminf(D.z, XFORM_CLIP);
        float dh = fminf(D.w, XFORM_CLIP);
        float pcx = __fadd_rn(__fmul_rn(D.x, w_), cx);
        float pcy = __fadd_rn(__fmul_rn(D.y, h_), cy);
        float pw  = __fmul_rn(__nv_expf(dw), w_);
        float ph  = __fmul_rn(__nv_expf(dh), h_);
        float hx = __fmul_rn(0.5f, pw), hy = __fmul_rn(0.5f, ph);
        float x1 = __fsub_rn(pcx, hx);
        float y1 = __fsub_rn(pcy, hy);
        float x2 = __fsub_rn(__fadd_rn(pcx, hx), 1.0f);
        float y2 = __fsub_rn(__fadd_rn(pcy, hy), 1.0f);
        x1 = fminf(fmaxf(x1, 0.0f), XMAX);
        x2 = fminf(fmaxf(x2, 0.0f), XMAX);
        y1 = fminf(fmaxf(y1, 0.0f), YMAX);
        y2 = fminf(fmaxf(y2, 0.0f), YMAX);
        float ww = __fadd_rn(__fsub_rn(x2, x1), 1.0f);
        float hh = __fadd_rn(__fsub_rn(y2, y1), 1.0f);
        g_props4[img * K_PRE + r2] = make_float4(x1, y1, x2, y2);
        g_area[img * K_PRE + r2] = __fmul_rn(ww, hh);
        g_valid[img * K_PRE + r2] = (ww >= 0.0f && hh >= 0.0f) ? 1 : 0;
        g_scores[img * K_PRE + r2] = score;
    }
    if (t == 0) g_state[img * 4 + 2] = 0u;
}

// ---------------- IoU test (div-free fast path, exact fallback) ----------------
__device__ __forceinline__ bool iou_sup(float4 a, float ai, float4 b, float aj) {
    float lx = fmaxf(a.x, b.x), ly = fmaxf(a.y, b.y);
    float rx = fminf(a.z, b.z), ry = fminf(a.w, b.w);
    float iw = fmaxf(__fadd_rn(__fsub_rn(rx, lx), 1.0f), 0.0f);
    float ih = fmaxf(__fadd_rn(__fsub_rn(ry, ly), 1.0f), 0.0f);
    float inter = __fmul_rn(iw, ih);
    float den = __fsub_rn(__fadd_rn(ai, aj), inter);
    float t = __fmaf_rn(-NMS_THRESH, den, inter);
    if (fabsf(t) <= __fmul_rn(1.2e-7f, den))
        return __fdiv_rn(inter, den) > NMS_THRESH;   // exact, rare
    return t > 0.0f;
}

// ---------------- fused mask + last-block greedy/pack ----------------
struct __align__(16) SMG {
    union {
        struct { float4 rbox[64]; float rar[64]; } m;
        struct { ull buf[2][2048]; unsigned char sk[2048]; } g;
    } u;
    int wsum[8];
    int stot;
    int done;
    unsigned int ticket;
};

__global__ void __launch_bounds__(256, 5) maskgreedy_kernel(float* __restrict__ out) {
    __shared__ SMG s;
    int img = blockIdx.y;
    int uu = blockIdx.x;                 // 0..527 upper-tri tiles
    int rb = 0, rem = uu;
    while (rem >= 32 - rb) { rem -= 32 - rb; rb++; }
    int cb = rb + rem;
    int t = threadIdx.x, wid = t >> 5, lane = t & 31;
    int r0 = rb * 64, j0 = cb * 64;
    if (t < 64) {
        int r = r0 + t;
        if (r < K_PRE) { s.u.m.rbox[t] = g_props4[img * K_PRE + r]; s.u.m.rar[t] = g_area[img * K_PRE + r]; }
        else           { s.u.m.rbox[t] = make_float4(1e9f, 1e9f, -1e9f, -1e9f); s.u.m.rar[t] = 1.0f; }
    }
    int jA = j0 + lane, jB = jA + 32;
    float4 bA = (jA < K_PRE) ? g_props4[img * K_PRE + jA] : make_float4(1e9f, 1e9f, -1e9f, -1e9f);
    float4 bB = (jB < K_PRE) ? g_props4[img * K_PRE + jB] : make_float4(1e9f, 1e9f, -1e9f, -1e9f);
    float aA = (jA < K_PRE) ? g_area[img * K_PRE + jA] : 1.0f;
    float aB = (jB < K_PRE) ? g_area[img * K_PRE + jB] : 1.0f;
    __syncthreads();
    bool diag = (cb == rb);
    // warp-per-row, rows from smem per iteration (measured-good form: issue 86%)
    for (int rr = wid; rr < 64; rr += 8) {
        int row = r0 + rr;
        float4 a = s.u.m.rbox[rr];
        float ai = s.u.m.rar[rr];
        bool sA = iou_sup(a, ai, bA, aA);
        bool sB = iou_sup(a, ai, bB, aB);
        if (diag) { sA = sA && (jA > row); sB = sB && (jB > row); }
        unsigned int lo = __ballot_sync(0xFFFFFFFFu, sA);
        unsigned int hi = __ballot_sync(0xFFFFFFFFu, sB);
        if (lane == 0)
            g_mask[((size_t)img * 2048 + row) * 32 + cb] = (ull)lo | ((ull)hi << 32);
    }
    // ---- ticket: last block of this image runs greedy + pack ----
    __threadfence();
    __syncthreads();
    if (t == 0) s.ticket = atomicAdd(&g_done3[img], 1u);
    __syncthreads();
    if (s.ticket != gridDim.x - 1) return;
    if (t == 0) g_done3[img] = 0u;

    const ull* M = &g_mask[(size_t)img * 2048 * 32];
    // chunk-0 load via cp.async (16B), no LDG->STS register chain
    for (int i = t; i < 2048; i += 256) s.u.g.sk[i] = 0;
    {
        const ulonglong2* src2 = (const ulonglong2*)M;
        ulonglong2* dst2 = (ulonglong2*)s.u.g.buf[0];
        for (int i = t; i < 1024; i += 256)
            __pipeline_memcpy_async(&dst2[i], &src2[i], 16);
        __pipeline_commit();
        __pipeline_wait_prior(0);
    }
    if (t == 0) s.done = 0;
    __syncthreads();
    ull removed = 0ull;
    if (wid == 0) {
        const ull* v8 = (const ull*)(g_valid + img * K_PRE);
        #pragma unroll
        for (int w = 0; w < 8; w++) {
            int wi = lane * 8 + w;
            ull x = (wi < K_PRE / 8) ? v8[wi] : 0ull;
            #pragma unroll
            for (int b = 0; b < 8; b++)
                if (!((x >> (8 * b)) & 0xFFull)) removed |= 1ull << (w * 8 + b);
        }
    }
    int nk = 0;
    for (int c = 0; c < 32; c++) {
        int cbuf = c & 1, nbuf = cbuf ^ 1;
        if (wid > 0 && (c + 1) < 32) {
            // cp.async prefetch of next chunk: issue-cost only, zero reg pressure
            const ulonglong2* src2 = (const ulonglong2*)&M[(size_t)(c + 1) * 2048];
            ulonglong2* dst2 = (ulonglong2*)s.u.g.buf[nbuf];
            for (int i = t - 32; i < 1024; i += 224)
                __pipeline_memcpy_async(&dst2[i], &src2[i], 16);
            __pipeline_commit();
            __pipeline_wait_prior(0);
        }
        if (wid == 0) {
            ull cur = __shfl_sync(0xFFFFFFFFu, removed, c);
            int base = c * 64;
            int lim = K_PRE - base; if (lim > 64) lim = 64;
            for (int qb = 0; qb < lim; qb += 8) {
                ull dw[8];
                #pragma unroll
                for (int r = 0; r < 8; r++)
                    dw[r] = s.u.g.buf[cbuf][(qb + r) * 32 + c];
                #pragma unroll
                for (int r = 0; r < 8; r++) {
                    int q = qb + r;
                    if (q < lim && nk < K_POST && !((cur >> q) & 1ull)) {
                        if (lane == 0) s.u.g.sk[base + q] = 1;
                        removed |= s.u.g.buf[cbuf][q * 32 + lane];
                        cur |= dw[r];
                        nk++;
                    }
                }
            }
            if (nk >= K_POST && lane == 0) s.done = 1;
        }
        __syncthreads();
        if (s.done) break;
    }
    // ---- fused stable-partition + pack (256 threads x 8 rows) ----
    ull f8 = ((const ull*)s.u.g.sk)[t];
    int sc = __popcll(f8);
    int v = sc;
    #pragma unroll
    for (int off = 1; off < 32; off <<= 1) {
        int n = __shfl_up_sync(0xFFFFFFFFu, v, off);
        if (lane >= off) v += n;
    }
    if (lane == 31) s.wsum[wid] = v;
    __syncthreads();
    if (wid == 0 && lane < 8) {
        int w = s.wsum[lane];
        #pragma unroll
        for (int off = 1; off < 8; off <<= 1) {
            int n = __shfl_up_sync(0xFFu, w, off);
            if ((int)lane >= off) w += n;
        }
        s.wsum[lane] = w;
        if (lane == 7) s.stot = w;
    }
    __syncthreads();
    int base8 = (wid > 0 ? s.wsum[wid - 1] : 0) + (v - sc);
    int total = s.stot;
    #pragma unroll
    for (int qq = 0; qq < 8; qq++) {
        int rr = t * 8 + qq;
        if (rr >= K_PRE) break;
        int flag = (int)((f8 >> (8 * qq)) & 1ull);
        ull low = (qq == 0) ? 0ull : (f8 & ((1ull << (8 * qq)) - 1ull));
        int kb = base8 + __popcll(low);
        int p = flag ? kb : total + (rr - kb);
        if (p < K_POST) {
            float4 P = g_props4[img * K_PRE + rr];
            float* o = &out[((size_t)img * K_POST + p) * 5];
            o[0] = P.x; o[1] = P.y; o[2] = P.z; o[3] = P.w;
            o[4] = flag ? g_scores[img * K_PRE + rr] : NEG_BIG;
        }
    }
}

// ---------------- launch ----------------
extern "C" void kernel_launch(void* const* d_in, const int* in_sizes, int n_in,
                              void* d_out, int out_size) {
    const float *anchors = nullptr, *obj = nullptr, *deltas = nullptr;
    for (int i = 0; i < n_in; i++) {
        if (in_sizes[i] == N_ANCH * 4)              anchors = (const float*)d_in[i];
        else if (in_sizes[i] == N_IMG * N_ANCH)     obj     = (const float*)d_in[i];
        else if (in_sizes[i] == N_IMG * N_ANCH * 4) deltas  = (const float*)d_in[i];
    }
    float* out = (float*)d_out;

    hist_kernel<<<dim3(31, N_IMG), 256>>>((const float4*)obj);
    compact_kernel<<<dim3(31, N_IMG), 256>>>((const float4*)obj);
    sortdec_kernel<<<N_IMG, 1024>>>(anchors, deltas);
    maskgreedy_kernel<<<dim3(528, N_IMG), 256>>>(out);
    (void)out_size;
}

// round 12
// speedup vs baseline: 1.1346x; 1.1346x over previous
#include <cuda_runtime.h>
#include <cstdint>

// libdevice precise expf (what XLA lowers jnp.exp(f32) to), immune to fast-math.
extern "C" __device__ float __nv_expf(float);

typedef unsigned long long ull;

// ---------------- problem constants ----------------
#define N_IMG 8
#define N_ANCH 250000
#define N_ANCH4 62500
#define K_PRE 2000
#define K_POST 1000
#define CAND_CAP 4096
#define NMS_THRESH 0.7f
#define XFORM_CLIP 4.135166556742356f
#define XMAX 1332.0f
#define YMAX 799.0f
#define NEG_BIG -1e9f
#define NBINS 4096
#define NB2 1024            // refined bins (512 in-bin + overflow)

// ---------------- device scratch (zero-init at load; self-cleaning per replay) ----------------
__device__ unsigned int g_hist[N_IMG * NBINS];
__device__ unsigned int g_hist2[N_IMG * NB2];
__device__ unsigned int g_done[N_IMG];
__device__ unsigned int g_done3[N_IMG];
__device__ unsigned int g_state[N_IMG * 4];      // [0]=coarse threshold key, [2]=cand_cnt
__device__ ull    g_cand[N_IMG * CAND_CAP];
__device__ float4 g_props4[N_IMG * K_PRE];
__device__ float  g_area[N_IMG * K_PRE];
__device__ float  g_scores[N_IMG * K_PRE];
__device__ unsigned char g_valid[N_IMG * K_PRE];
__device__ ull    g_mask[N_IMG * 2048 * 32];

__device__ __forceinline__ unsigned int okey_of(float f) {
    unsigned int b = __float_as_uint(f);
    return b ^ ((b & 0x80000000u) ? 0xFFFFFFFFu : 0x80000000u);
}

// ---------------- histogram (12-bit bins) + fused last-block threshold scan ----------------
__global__ void hist_kernel(const float4* __restrict__ obj4) {
    int img = blockIdx.y, t = threadIdx.x;
    __shared__ unsigned int sh[2][NBINS];
    __shared__ unsigned int s_ticket;
    __shared__ unsigned int wsums[8];
    for (int i = t; i < 2 * NBINS; i += 256) ((unsigned int*)sh)[i] = 0u;
    __syncthreads();
    const float4* o = obj4 + (size_t)img * N_ANCH4;
    int base = blockIdx.x * 2048 + t;
    float4 v[8]; bool m[8];
    #pragma unroll
    for (int u = 0; u < 8; u++) {
        int i = base + u * 256;
        m[u] = (i < N_ANCH4);
        v[u] = m[u] ? o[i] : make_float4(0.f, 0.f, 0.f, 0.f);
    }
    int p = (t >> 5) & 1;
    #pragma unroll
    for (int u = 0; u < 8; u++) if (m[u]) {
        atomicAdd(&sh[p][okey_of(v[u].x) >> 20], 1u);
        atomicAdd(&sh[p][okey_of(v[u].y) >> 20], 1u);
        atomicAdd(&sh[p][okey_of(v[u].z) >> 20], 1u);
        atomicAdd(&sh[p][okey_of(v[u].w) >> 20], 1u);
    }
    __syncthreads();
    for (int i = t; i < NBINS; i += 256) {
        unsigned int s = sh[0][i] + sh[1][i];
        if (s) atomicAdd(&g_hist[img * NBINS + i], s);
    }
    // ---- last-block coarse threshold scan (fence + ticket) ----
    __threadfence();
    __syncthreads();
    if (t == 0) s_ticket = atomicAdd(&g_done[img], 1u);
    __syncthreads();
    if (s_ticket == gridDim.x - 1) {
        int lane = t & 31, wid = t >> 5;
        int r0 = t * 16;                     // descending positions; bin = 4095 - r
        unsigned int cc[16], s[16];
        #pragma unroll
        for (int u = 0; u < 16; u++)
            cc[u] = __ldcg(&g_hist[img * NBINS + (NBINS - 1 - (r0 + u))]);
        unsigned int run = 0;
        #pragma unroll
        for (int u = 0; u < 16; u++) { run += cc[u]; s[u] = run; }
        unsigned int vv = run;
        #pragma unroll
        for (int off = 1; off < 32; off <<= 1) {
            unsigned int n = __shfl_up_sync(0xFFFFFFFFu, vv, off);
            if (lane >= off) vv += n;
        }
        if (lane == 31) wsums[wid] = vv;
        __syncthreads();
        if (wid == 0 && lane < 8) {
            unsigned int w = wsums[lane];
            #pragma unroll
            for (int off = 1; off < 8; off <<= 1) {
                unsigned int n = __shfl_up_sync(0xFFu, w, off);
                if ((int)lane >= off) w += n;
            }
            wsums[lane] = w;
        }
        __syncthreads();
        unsigned int excl = (wid > 0 ? wsums[wid - 1] : 0u) + (vv - run);
        if (excl < K_PRE && excl + run >= K_PRE) {
            int u = 0;
            #pragma unroll
            for (int q = 15; q >= 0; q--) if (excl + s[q] >= K_PRE) u = q;
            g_state[img * 4 + 0] = (unsigned int)(NBINS - 1 - (r0 + u)) << 20;
        }
        #pragma unroll
        for (int u = 0; u < 16; u++)
            g_hist[img * NBINS + (NBINS - 1 - (r0 + u))] = 0u;
        if (t == 0) g_done[img] = 0u;
    }
}

// ---------------- compact candidates + refined 21-bit histogram ----------------
__global__ void compact_kernel(const float4* __restrict__ obj4) {
    int img = blockIdx.y, t = threadIdx.x;
    __shared__ unsigned int h2[NB2];
    #pragma unroll
    for (int u = 0; u < 4; u++) h2[t + u * 256] = 0u;
    __syncthreads();
    unsigned int T = g_state[img * 4 + 0];
    unsigned int T11 = T >> 11;
    const float4* o = obj4 + (size_t)img * N_ANCH4;
    int base = blockIdx.x * 2048 + t;
    float4 v[8]; bool m[8];
    #pragma unroll
    for (int u = 0; u < 8; u++) {
        int i = base + u * 256;
        m[u] = (i < N_ANCH4);
        v[u] = m[u] ? o[i] : make_float4(0.f, 0.f, 0.f, 0.f);
    }
    #pragma unroll
    for (int u = 0; u < 8; u++) if (m[u]) {
        int i = base + u * 256;
        #pragma unroll
        for (int c = 0; c < 4; c++) {
            float f = (c == 0) ? v[u].x : (c == 1) ? v[u].y : (c == 2) ? v[u].z : v[u].w;
            unsigned int k = okey_of(f);
            if (k >= T) {
                unsigned int d = (k >> 11) - T11; if (d > NB2 - 1) d = NB2 - 1;
                atomicAdd(&h2[d], 1u);
                unsigned int pos = atomicAdd(&g_state[img * 4 + 2], 1u);
                if (pos < CAND_CAP)
                    g_cand[img * CAND_CAP + pos] =
                        ((ull)k << 32) | (unsigned int)(~(unsigned int)(4 * i + c));
            }
        }
    }
    __syncthreads();
    #pragma unroll
    for (int u = 0; u < 4; u++) {
        unsigned int s = h2[t + u * 256];
        if (s) atomicAdd(&g_hist2[img * NB2 + t + u * 256], s);
    }
}

// ---------------- sortdec: refined select + V=2 bitonic + decode ----------------
__device__ __forceinline__ void cas_reg(ull& a, ull& b, bool desc) {
    if ((a < b) == desc) { ull tmp = a; a = b; b = tmp; }
}

__global__ void sortdec_kernel(const float* __restrict__ anchors,
                               const float* __restrict__ deltas) {
    int img = blockIdx.x, t = threadIdx.x;   // 1024 threads
    __shared__ ull sh[CAND_CAP];             // 32 KB
    __shared__ unsigned int wsums[32];
    __shared__ int sT2;
    __shared__ int c2cnt;
    int w = t >> 5, lane = t & 31;
    unsigned int cnt = g_state[img * 4 + 2];
    if (cnt > CAND_CAP) cnt = CAND_CAP;
    if (t == 0) c2cnt = 0;
    ull v[4];
    #pragma unroll
    for (int u = 0; u < 4; u++) {
        int i = t + u * 1024;
        v[u] = (i < (int)cnt) ? g_cand[img * CAND_CAP + i] : 0ull;
    }
    unsigned int c = __ldcg(&g_hist2[img * NB2 + (NB2 - 1 - t)]);
    g_hist2[img * NB2 + (NB2 - 1 - t)] = 0u;   // self-clean for next replay
    unsigned int vv = c;
    #pragma unroll
    for (int off = 1; off < 32; off <<= 1) {
        unsigned int n = __shfl_up_sync(0xFFFFFFFFu, vv, off);
        if (lane >= off) vv += n;
    }
    if (lane == 31) wsums[w] = vv;
    __syncthreads();
    if (w == 0) {
        unsigned int x = wsums[lane];
        #pragma unroll
        for (int off = 1; off < 32; off <<= 1) {
            unsigned int n = __shfl_up_sync(0xFFFFFFFFu, x, off);
            if (lane >= off) x += n;
        }
        wsums[lane] = x;
    }
    __syncthreads();
    unsigned int excl = (w > 0 ? wsums[w - 1] : 0u) + (vv - c);
    if (excl < K_PRE && excl + c >= K_PRE) sT2 = NB2 - 1 - t;
    __syncthreads();
    unsigned int T11 = g_state[img * 4 + 0] >> 11;
    unsigned int dstar = (unsigned int)sT2;
    #pragma unroll
    for (int u = 0; u < 4; u++) {
        int i = t + u * 1024;
        unsigned int k = (unsigned int)(v[u] >> 32);
        unsigned int d = (k >> 11) - T11; if (d > NB2 - 1) d = NB2 - 1;
        bool p = (i < (int)cnt) && (d >= dstar);
        unsigned int ball = __ballot_sync(0xFFFFFFFFu, p);
        int bpos = 0;
        if (lane == 0 && ball) bpos = atomicAdd(&c2cnt, __popc(ball));
        bpos = __shfl_sync(0xFFFFFFFFu, bpos, 0);
        if (p) sh[bpos + __popc(ball & ((1u << lane) - 1u))] = v[u];
    }
    __syncthreads();
    int C2 = c2cnt;
    if (C2 <= 2048) {
        for (int i = t; i < 2048; i += 1024) if (i >= C2) sh[i] = 0ull;
        __syncthreads();
        ull r[2];
        #pragma unroll
        for (int e = 0; e < 2; e++) r[e] = sh[(w << 6) | (e << 5) | lane];
        for (int k = 2; k <= 2048; k <<= 1) {
            if (k >= 128) {
                #pragma unroll
                for (int e = 0; e < 2; e++) sh[(w << 6) | (e << 5) | lane] = r[e];
                __syncthreads();
                for (int j = k >> 1; j >= 64; j >>= 1) {
                    int i = ((t & ~(j - 1)) << 1) | (t & (j - 1));
                    int ixj = i | j;
                    bool desc = ((i & k) == 0);
                    ull A = sh[i], B = sh[ixj];
                    if ((A < B) == desc) { sh[i] = B; sh[ixj] = A; }
                    __syncthreads();
                }
                #pragma unroll
                for (int e = 0; e < 2; e++) r[e] = sh[(w << 6) | (e << 5) | lane];
            }
            if (k >= 64) {
                bool d = (((w << 6) & k) == 0);
                cas_reg(r[0], r[1], d);
            }
            int jmax = (k >> 1) < 16 ? (k >> 1) : 16;
            for (int j = jmax; j >= 1; j >>= 1) {
                #pragma unroll
                for (int e = 0; e < 2; e++) {
                    int i = (w << 6) | (e << 5) | lane;
                    bool desc = ((i & k) == 0);
                    bool iLow = ((lane & j) == 0);
                    ull p2 = __shfl_xor_sync(0xFFFFFFFFu, r[e], j);
                    ull mx = (r[e] > p2) ? r[e] : p2;
                    ull mn = (r[e] > p2) ? p2 : r[e];
                    r[e] = (iLow == desc) ? mx : mn;
                }
            }
        }
        #pragma unroll
        for (int e = 0; e < 2; e++) sh[(w << 6) | (e << 5) | lane] = r[e];
        __syncthreads();
    } else {
        for (int i = t; i < CAND_CAP; i += 1024)
            sh[i] = (i < (int)cnt) ? g_cand[img * CAND_CAP + i] : 0ull;
        __syncthreads();
        for (int k = 2; k <= CAND_CAP; k <<= 1) {
            for (int j = k >> 1; j > 0; j >>= 1) {
                for (int i = t; i < CAND_CAP; i += 1024) {
                    int ixj = i ^ j;
                    if (ixj > i) {
                        bool desc = ((i & k) == 0);
                        ull A = sh[i], B = sh[ixj];
                        if (desc ? (A < B) : (A > B)) { sh[i] = B; sh[ixj] = A; }
                    }
                }
                __syncthreads();
            }
        }
    }
    for (int r2 = t; r2 < K_PRE; r2 += 1024) {
        ull e = sh[r2];
        int idx = (int)(~(unsigned int)(e & 0xFFFFFFFFull));
        unsigned int kk = (unsigned int)(e >> 32);
        float score = __uint_as_float((kk & 0x80000000u) ? (kk ^ 0x80000000u) : ~kk);
        const float4 A = ((const float4*)anchors)[idx];
        const float4 D = ((const float4*)deltas)[(size_t)img * N_ANCH + idx];
        float w_  = __fadd_rn(__fsub_rn(A.z, A.x), 1.0f);
        float h_  = __fadd_rn(__fsub_rn(A.w, A.y), 1.0f);
        float cx = __fadd_rn(A.x, __fmul_rn(0.5f, w_));
        float cy = __fadd_rn(A.y, __fmul_rn(0.5f, h_));
        float dw = fminf(D.z, XFORM_CLIP);
        float dh = fminf(D.w, XFORM_CLIP);
        float pcx = __fadd_rn(__fmul_rn(D.x, w_), cx);
        float pcy = __fadd_rn(__fmul_rn(D.y, h_), cy);
        float pw  = __fmul_rn(__nv_expf(dw), w_);
        float ph  = __fmul_rn(__nv_expf(dh), h_);
        float hx = __fmul_rn(0.5f, pw), hy = __fmul_rn(0.5f, ph);
        float x1 = __fsub_rn(pcx, hx);
        float y1 = __fsub_rn(pcy, hy);
        float x2 = __fsub_rn(__fadd_rn(pcx, hx), 1.0f);
        float y2 = __fsub_rn(__fadd_rn(pcy, hy), 1.0f);
        x1 = fminf(fmaxf(x1, 0.0f), XMAX);
        x2 = fminf(fmaxf(x2, 0.0f), XMAX);
        y1 = fminf(fmaxf(y1, 0.0f), YMAX);
        y2 = fminf(fmaxf(y2, 0.0f), YMAX);
        float ww = __fadd_rn(__fsub_rn(x2, x1), 1.0f);
        float hh = __fadd_rn(__fsub_rn(y2, y1), 1.0f);
        g_props4[img * K_PRE + r2] = make_float4(x1, y1, x2, y2);
        g_area[img * K_PRE + r2] = __fmul_rn(ww, hh);
        g_valid[img * K_PRE + r2] = (ww >= 0.0f && hh >= 0.0f) ? 1 : 0;
        g_scores[img * K_PRE + r2] = score;
    }
    if (t == 0) g_state[img * 4 + 2] = 0u;
}

// ---------------- IoU test (div-free fast path, exact fallback) ----------------
__device__ __forceinline__ bool iou_sup(float4 a, float ai, float4 b, float aj) {
    float lx = fmaxf(a.x, b.x), ly = fmaxf(a.y, b.y);
    float rx = fminf(a.z, b.z), ry = fminf(a.w, b.w);
    float iw = fmaxf(__fadd_rn(__fsub_rn(rx, lx), 1.0f), 0.0f);
    float ih = fmaxf(__fadd_rn(__fsub_rn(ry, ly), 1.0f), 0.0f);
    float inter = __fmul_rn(iw, ih);
    float den = __fsub_rn(__fadd_rn(ai, aj), inter);
    float t = __fmaf_rn(-NMS_THRESH, den, inter);
    if (fabsf(t) <= __fmul_rn(1.2e-7f, den))
        return __fdiv_rn(inter, den) > NMS_THRESH;   // exact, rare
    return t > 0.0f;
}

// ---------------- fused mask + last-block greedy/pack ----------------
struct __align__(16) SMG {
    union {
        struct { float4 rbox[64]; float rar[64]; } m;
        struct { ull buf[2][2048]; unsigned char sk[2048]; } g;
    } u;
    int wsum[8];
    int stot;
    int done;
    unsigned int ticket;
};

__global__ void __launch_bounds__(256, 4) maskgreedy_kernel(float* __restrict__ out) {
    __shared__ SMG s;
    int img = blockIdx.y;
    int uu = blockIdx.x;                 // 0..527 upper-tri tiles
    int rb = 0, rem = uu;
    while (rem >= 32 - rb) { rem -= 32 - rb; rb++; }
    int cb = rb + rem;
    int t = threadIdx.x, wid = t >> 5, lane = t & 31;
    int r0 = rb * 64, j0 = cb * 64;
    if (t < 64) {
        int r = r0 + t;
        if (r < K_PRE) { s.u.m.rbox[t] = g_props4[img * K_PRE + r]; s.u.m.rar[t] = g_area[img * K_PRE + r]; }
        else           { s.u.m.rbox[t] = make_float4(1e9f, 1e9f, -1e9f, -1e9f); s.u.m.rar[t] = 1.0f; }
    }
    int jA = j0 + lane, jB = jA + 32;
    float4 bA = (jA < K_PRE) ? g_props4[img * K_PRE + jA] : make_float4(1e9f, 1e9f, -1e9f, -1e9f);
    float4 bB = (jB < K_PRE) ? g_props4[img * K_PRE + jB] : make_float4(1e9f, 1e9f, -1e9f, -1e9f);
    float aA = (jA < K_PRE) ? g_area[img * K_PRE + jA] : 1.0f;
    float aB = (jB < K_PRE) ? g_area[img * K_PRE + jB] : 1.0f;
    __syncthreads();
    bool diag = (cb == rb);
    // warp-per-row, rows from smem per iteration (measured-good form: issue 86%)
    for (int rr = wid; rr < 64; rr += 8) {
        int row = r0 + rr;
        float4 a = s.u.m.rbox[rr];
        float ai = s.u.m.rar[rr];
        bool sA = iou_sup(a, ai, bA, aA);
        bool sB = iou_sup(a, ai, bB, aB);
        if (diag) { sA = sA && (jA > row); sB = sB && (jB > row); }
        unsigned int lo = __ballot_sync(0xFFFFFFFFu, sA);
        unsigned int hi = __ballot_sync(0xFFFFFFFFu, sB);
        if (lane == 0)
            g_mask[((size_t)img * 2048 + row) * 32 + cb] = (ull)lo | ((ull)hi << 32);
    }
    // ---- ticket: last block of this image runs greedy + pack ----
    __threadfence();
    __syncthreads();
    if (t == 0) s.ticket = atomicAdd(&g_done3[img], 1u);
    __syncthreads();
    if (s.ticket != gridDim.x - 1) return;
    if (t == 0) g_done3[img] = 0u;

    const ull* M = &g_mask[(size_t)img * 2048 * 32];
    // chunk-0 load: register-batched __ldcg (MLP=8)
    for (int i = t; i < 2048; i += 256) s.u.g.sk[i] = 0;
    {
        ull tmp0[8];
        #pragma unroll
        for (int u = 0; u < 8; u++) tmp0[u] = __ldcg(&M[t + u * 256]);
        #pragma unroll
        for (int u = 0; u < 8; u++) s.u.g.buf[0][t + u * 256] = tmp0[u];
    }
    if (t == 0) s.done = 0;
    __syncthreads();
    ull removed = 0ull;
    if (wid == 0) {
        const ull* v8 = (const ull*)(g_valid + img * K_PRE);
        #pragma unroll
        for (int w = 0; w < 8; w++) {
            int wi = lane * 8 + w;
            ull x = (wi < K_PRE / 8) ? v8[wi] : 0ull;
            #pragma unroll
            for (int b = 0; b < 8; b++)
                if (!((x >> (8 * b)) & 0xFFull)) removed |= 1ull << (w * 8 + b);
        }
    }
    int nk = 0;
    for (int c = 0; c < 32; c++) {
        int cbuf = c & 1, nbuf = cbuf ^ 1;
        if (wid > 0 && (c + 1) < 32) {
            // register-batched prefetch: issue all LDGs (MLP~10), then store
            const ull* src = &M[(size_t)(c + 1) * 2048];
            ull tmp[10];
            #pragma unroll
            for (int u = 0; u < 10; u++) {
                int i = (t - 32) + u * 224;
                tmp[u] = (i < 2048) ? __ldcg(&src[i]) : 0ull;
            }
            #pragma unroll
            for (int u = 0; u < 10; u++) {
                int i = (t - 32) + u * 224;
                if (i < 2048) s.u.g.buf[nbuf][i] = tmp[u];
            }
        }
        if (wid == 0) {
            ull cur = __shfl_sync(0xFFFFFFFFu, removed, c);
            int base = c * 64;
            int lim = K_PRE - base; if (lim > 64) lim = 64;
            for (int qb = 0; qb < lim; qb += 8) {
                ull dw[8];
                #pragma unroll
                for (int r = 0; r < 8; r++)
                    dw[r] = s.u.g.buf[cbuf][(qb + r) * 32 + c];
                #pragma unroll
                for (int r = 0; r < 8; r++) {
                    int q = qb + r;
                    if (q < lim && nk < K_POST && !((cur >> q) & 1ull)) {
                        if (lane == 0) s.u.g.sk[base + q] = 1;
                        removed |= s.u.g.buf[cbuf][q * 32 + lane];
                        cur |= dw[r];
                        nk++;
                    }
                }
            }
            if (nk >= K_POST && lane == 0) s.done = 1;
        }
        __syncthreads();
        if (s.done) break;
    }
    // ---- fused stable-partition + pack (256 threads x 8 rows) ----
    ull f8 = ((const ull*)s.u.g.sk)[t];
    int sc = __popcll(f8);
    int v = sc;
    #pragma unroll
    for (int off = 1; off < 32; off <<= 1) {
        int n = __shfl_up_sync(0xFFFFFFFFu, v, off);
        if (lane >= off) v += n;
    }
    if (lane == 31) s.wsum[wid] = v;
    __syncthreads();
    if (wid == 0 && lane < 8) {
        int w = s.wsum[lane];
        #pragma unroll
        for (int off = 1; off < 8; off <<= 1) {
            int n = __shfl_up_sync(0xFFu, w, off);
            if ((int)lane >= off) w += n;
        }
        s.wsum[lane] = w;
        if (lane == 7) s.stot = w;
    }
    __syncthreads();
    int base8 = (wid > 0 ? s.wsum[wid - 1] : 0) + (v - sc);
    int total = s.stot;
    #pragma unroll
    for (int qq = 0; qq < 8; qq++) {
        int rr = t * 8 + qq;
        if (rr >= K_PRE) break;
        int flag = (int)((f8 >> (8 * qq)) & 1ull);
        ull low = (qq == 0) ? 0ull : (f8 & ((1ull << (8 * qq)) - 1ull));
        int kb = base8 + __popcll(low);
        int p = flag ? kb : total + (rr - kb);
        if (p < K_POST) {
            float4 P = g_props4[img * K_PRE + rr];
            float* o = &out[((size_t)img * K_POST + p) * 5];
            o[0] = P.x; o[1] = P.y; o[2] = P.z; o[3] = P.w;
            o[4] = flag ? g_scores[img * K_PRE + rr] : NEG_BIG;
        }
    }
}

// ---------------- launch ----------------
extern "C" void kernel_launch(void* const* d_in, const int* in_sizes, int n_in,
                              void* d_out, int out_size) {
    const float *anchors = nullptr, *obj = nullptr, *deltas = nullptr;
    for (int i = 0; i < n_in; i++) {
        if (in_sizes[i] == N_ANCH * 4)              anchors = (const float*)d_in[i];
        else if (in_sizes[i] == N_IMG * N_ANCH)     obj     = (const float*)d_in[i];
        else if (in_sizes[i] == N_IMG * N_ANCH * 4) deltas  = (const float*)d_in[i];
    }
    float* out = (float*)d_out;

    hist_kernel<<<dim3(31, N_IMG), 256>>>((const float4*)obj);
    compact_kernel<<<dim3(31, N_IMG), 256>>>((const float4*)obj);
    sortdec_kernel<<<N_IMG, 1024>>>(anchors, deltas);
    maskgreedy_kernel<<<dim3(528, N_IMG), 256>>>(out);
    (void)out_size;
}

// round 13
// speedup vs baseline: 1.3417x; 1.1825x over previous
#include <cuda_runtime.h>
#include <cstdint>

// libdevice precise expf (what XLA lowers jnp.exp(f32) to), immune to fast-math.
extern "C" __device__ float __nv_expf(float);

typedef unsigned long long ull;

// ---------------- problem constants ----------------
#define N_IMG 8
#define N_ANCH 250000
#define N_ANCH4 62500
#define K_PRE 2000
#define K_POST 1000
#define CAND_CAP 4096
#define NMS_THRESH 0.7f
#define XFORM_CLIP 4.135166556742356f
#define XMAX 1332.0f
#define YMAX 799.0f
#define NEG_BIG -1e9f
#define NBINS 4096
#define NB2 1024            // refined bins (512 in-bin + overflow)

// ---------------- device scratch (zero-init at load; self-cleaning per replay) ----------------
__device__ unsigned int g_hist[N_IMG * NBINS];
__device__ unsigned int g_hist2[N_IMG * NB2];
__device__ unsigned int g_done[N_IMG];
__device__ unsigned int g_done3[N_IMG];
__device__ unsigned int g_state[N_IMG * 4];      // [0]=coarse threshold key, [2]=cand_cnt
__device__ ull    g_cand[N_IMG * CAND_CAP];
__device__ float4 g_props4[N_IMG * K_PRE];
__device__ float  g_area[N_IMG * K_PRE];
__device__ float  g_scores[N_IMG * K_PRE];
__device__ unsigned char g_valid[N_IMG * K_PRE];
__device__ ull    g_mask[N_IMG * 2048 * 32];

__device__ __forceinline__ unsigned int okey_of(float f) {
    unsigned int b = __float_as_uint(f);
    return b ^ ((b & 0x80000000u) ? 0xFFFFFFFFu : 0x80000000u);
}

// ---------------- histogram (12-bit bins) + fused last-block threshold scan ----------------
__global__ void hist_kernel(const float4* __restrict__ obj4) {
    int img = blockIdx.y, t = threadIdx.x;
    __shared__ unsigned int sh[2][NBINS];
    __shared__ unsigned int s_ticket;
    __shared__ unsigned int wsums[8];
    for (int i = t; i < 2 * NBINS; i += 256) ((unsigned int*)sh)[i] = 0u;
    __syncthreads();
    const float4* o = obj4 + (size_t)img * N_ANCH4;
    int base = blockIdx.x * 2048 + t;
    float4 v[8]; bool m[8];
    #pragma unroll
    for (int u = 0; u < 8; u++) {
        int i = base + u * 256;
        m[u] = (i < N_ANCH4);
        v[u] = m[u] ? o[i] : make_float4(0.f, 0.f, 0.f, 0.f);
    }
    int p = (t >> 5) & 1;
    #pragma unroll
    for (int u = 0; u < 8; u++) if (m[u]) {
        atomicAdd(&sh[p][okey_of(v[u].x) >> 20], 1u);
        atomicAdd(&sh[p][okey_of(v[u].y) >> 20], 1u);
        atomicAdd(&sh[p][okey_of(v[u].z) >> 20], 1u);
        atomicAdd(&sh[p][okey_of(v[u].w) >> 20], 1u);
    }
    __syncthreads();
    for (int i = t; i < NBINS; i += 256) {
        unsigned int s = sh[0][i] + sh[1][i];
        if (s) atomicAdd(&g_hist[img * NBINS + i], s);
    }
    // ---- last-block coarse threshold scan (fence + ticket) ----
    __threadfence();
    __syncthreads();
    if (t == 0) s_ticket = atomicAdd(&g_done[img], 1u);
    __syncthreads();
    if (s_ticket == gridDim.x - 1) {
        int lane = t & 31, wid = t >> 5;
        int r0 = t * 16;                     // descending positions; bin = 4095 - r
        unsigned int cc[16], s[16];
        #pragma unroll
        for (int u = 0; u < 16; u++)
            cc[u] = __ldcg(&g_hist[img * NBINS + (NBINS - 1 - (r0 + u))]);
        unsigned int run = 0;
        #pragma unroll
        for (int u = 0; u < 16; u++) { run += cc[u]; s[u] = run; }
        unsigned int vv = run;
        #pragma unroll
        for (int off = 1; off < 32; off <<= 1) {
            unsigned int n = __shfl_up_sync(0xFFFFFFFFu, vv, off);
            if (lane >= off) vv += n;
        }
        if (lane == 31) wsums[wid] = vv;
        __syncthreads();
        if (wid == 0 && lane < 8) {
            unsigned int w = wsums[lane];
            #pragma unroll
            for (int off = 1; off < 8; off <<= 1) {
                unsigned int n = __shfl_up_sync(0xFFu, w, off);
                if ((int)lane >= off) w += n;
            }
            wsums[lane] = w;
        }
        __syncthreads();
        unsigned int excl = (wid > 0 ? wsums[wid - 1] : 0u) + (vv - run);
        if (excl < K_PRE && excl + run >= K_PRE) {
            int u = 0;
            #pragma unroll
            for (int q = 15; q >= 0; q--) if (excl + s[q] >= K_PRE) u = q;
            g_state[img * 4 + 0] = (unsigned int)(NBINS - 1 - (r0 + u)) << 20;
        }
        #pragma unroll
        for (int u = 0; u < 16; u++)
            g_hist[img * NBINS + (NBINS - 1 - (r0 + u))] = 0u;
        if (t == 0) g_done[img] = 0u;
    }
}

// ---------------- compact candidates + refined 21-bit histogram ----------------
__global__ void compact_kernel(const float4* __restrict__ obj4) {
    int img = blockIdx.y, t = threadIdx.x;
    __shared__ unsigned int h2[NB2];
    #pragma unroll
    for (int u = 0; u < 4; u++) h2[t + u * 256] = 0u;
    __syncthreads();
    unsigned int T = g_state[img * 4 + 0];
    unsigned int T11 = T >> 11;
    const float4* o = obj4 + (size_t)img * N_ANCH4;
    int base = blockIdx.x * 2048 + t;
    float4 v[8]; bool m[8];
    #pragma unroll
    for (int u = 0; u < 8; u++) {
        int i = base + u * 256;
        m[u] = (i < N_ANCH4);
        v[u] = m[u] ? o[i] : make_float4(0.f, 0.f, 0.f, 0.f);
    }
    #pragma unroll
    for (int u = 0; u < 8; u++) if (m[u]) {
        int i = base + u * 256;
        #pragma unroll
        for (int c = 0; c < 4; c++) {
            float f = (c == 0) ? v[u].x : (c == 1) ? v[u].y : (c == 2) ? v[u].z : v[u].w;
            unsigned int k = okey_of(f);
            if (k >= T) {
                unsigned int d = (k >> 11) - T11; if (d > NB2 - 1) d = NB2 - 1;
                atomicAdd(&h2[d], 1u);
                unsigned int pos = atomicAdd(&g_state[img * 4 + 2], 1u);
                if (pos < CAND_CAP)
                    g_cand[img * CAND_CAP + pos] =
                        ((ull)k << 32) | (unsigned int)(~(unsigned int)(4 * i + c));
            }
        }
    }
    __syncthreads();
    #pragma unroll
    for (int u = 0; u < 4; u++) {
        unsigned int s = h2[t + u * 256];
        if (s) atomicAdd(&g_hist2[img * NB2 + t + u * 256], s);
    }
}

// ---------------- sortdec: refined select + V=2 bitonic + decode ----------------
__device__ __forceinline__ void cas_reg(ull& a, ull& b, bool desc) {
    if ((a < b) == desc) { ull tmp = a; a = b; b = tmp; }
}

__global__ void sortdec_kernel(const float* __restrict__ anchors,
                               const float* __restrict__ deltas) {
    int img = blockIdx.x, t = threadIdx.x;   // 1024 threads
    __shared__ ull sh[CAND_CAP];             // 32 KB
    __shared__ unsigned int wsums[32];
    __shared__ int sT2;
    __shared__ int c2cnt;
    int w = t >> 5, lane = t & 31;
    unsigned int cnt = g_state[img * 4 + 2];
    if (cnt > CAND_CAP) cnt = CAND_CAP;
    if (t == 0) c2cnt = 0;
    ull v[4];
    #pragma unroll
    for (int u = 0; u < 4; u++) {
        int i = t + u * 1024;
        v[u] = (i < (int)cnt) ? g_cand[img * CAND_CAP + i] : 0ull;
    }
    unsigned int c = __ldcg(&g_hist2[img * NB2 + (NB2 - 1 - t)]);
    g_hist2[img * NB2 + (NB2 - 1 - t)] = 0u;   // self-clean for next replay
    unsigned int vv = c;
    #pragma unroll
    for (int off = 1; off < 32; off <<= 1) {
        unsigned int n = __shfl_up_sync(0xFFFFFFFFu, vv, off);
        if (lane >= off) vv += n;
    }
    if (lane == 31) wsums[w] = vv;
    __syncthreads();
    if (w == 0) {
        unsigned int x = wsums[lane];
        #pragma unroll
        for (int off = 1; off < 32; off <<= 1) {
            unsigned int n = __shfl_up_sync(0xFFFFFFFFu, x, off);
            if (lane >= off) x += n;
        }
        wsums[lane] = x;
    }
    __syncthreads();
    unsigned int excl = (w > 0 ? wsums[w - 1] : 0u) + (vv - c);
    if (excl < K_PRE && excl + c >= K_PRE) sT2 = NB2 - 1 - t;
    __syncthreads();
    unsigned int T11 = g_state[img * 4 + 0] >> 11;
    unsigned int dstar = (unsigned int)sT2;
    #pragma unroll
    for (int u = 0; u < 4; u++) {
        int i = t + u * 1024;
        unsigned int k = (unsigned int)(v[u] >> 32);
        unsigned int d = (k >> 11) - T11; if (d > NB2 - 1) d = NB2 - 1;
        bool p = (i < (int)cnt) && (d >= dstar);
        unsigned int ball = __ballot_sync(0xFFFFFFFFu, p);
        int bpos = 0;
        if (lane == 0 && ball) bpos = atomicAdd(&c2cnt, __popc(ball));
        bpos = __shfl_sync(0xFFFFFFFFu, bpos, 0);
        if (p) sh[bpos + __popc(ball & ((1u << lane) - 1u))] = v[u];
    }
    __syncthreads();
    int C2 = c2cnt;
    if (C2 <= 2048) {
        for (int i = t; i < 2048; i += 1024) if (i >= C2) sh[i] = 0ull;
        __syncthreads();
        ull r[2];
        #pragma unroll
        for (int e = 0; e < 2; e++) r[e] = sh[(w << 6) | (e << 5) | lane];
        for (int k = 2; k <= 2048; k <<= 1) {
            if (k >= 128) {
                #pragma unroll
                for (int e = 0; e < 2; e++) sh[(w << 6) | (e << 5) | lane] = r[e];
                __syncthreads();
                for (int j = k >> 1; j >= 64; j >>= 1) {
                    int i = ((t & ~(j - 1)) << 1) | (t & (j - 1));
                    int ixj = i | j;
                    bool desc = ((i & k) == 0);
                    ull A = sh[i], B = sh[ixj];
                    if ((A < B) == desc) { sh[i] = B; sh[ixj] = A; }
                    __syncthreads();
                }
                #pragma unroll
                for (int e = 0; e < 2; e++) r[e] = sh[(w << 6) | (e << 5) | lane];
            }
            if (k >= 64) {
                bool d = (((w << 6) & k) == 0);
                cas_reg(r[0], r[1], d);
            }
            int jmax = (k >> 1) < 16 ? (k >> 1) : 16;
            for (int j = jmax; j >= 1; j >>= 1) {
                #pragma unroll
                for (int e = 0; e < 2; e++) {
                    int i = (w << 6) | (e << 5) | lane;
                    bool desc = ((i & k) == 0);
                    bool iLow = ((lane & j) == 0);
                    ull p2 = __shfl_xor_sync(0xFFFFFFFFu, r[e], j);
                    ull mx = (r[e] > p2) ? r[e] : p2;
                    ull mn = (r[e] > p2) ? p2 : r[e];
                    r[e] = (iLow == desc) ? mx : mn;
                }
            }
        }
        #pragma unroll
        for (int e = 0; e < 2; e++) sh[(w << 6) | (e << 5) | lane] = r[e];
        __syncthreads();
    } else {
        for (int i = t; i < CAND_CAP; i += 1024)
            sh[i] = (i < (int)cnt) ? g_cand[img * CAND_CAP + i] : 0ull;
        __syncthreads();
        for (int k = 2; k <= CAND_CAP; k <<= 1) {
            for (int j = k >> 1; j > 0; j >>= 1) {
                for (int i = t; i < CAND_CAP; i += 1024) {
                    int ixj = i ^ j;
                    if (ixj > i) {
                        bool desc = ((i & k) == 0);
                        ull A = sh[i], B = sh[ixj];
                        if (desc ? (A < B) : (A > B)) { sh[i] = B; sh[ixj] = A; }
                    }
                }
                __syncthreads();
            }
        }
    }
    for (int r2 = t; r2 < K_PRE; r2 += 1024) {
        ull e = sh[r2];
        int idx = (int)(~(unsigned int)(e & 0xFFFFFFFFull));
        unsigned int kk = (unsigned int)(e >> 32);
        float score = __uint_as_float((kk & 0x80000000u) ? (kk ^ 0x80000000u) : ~kk);
        const float4 A = ((const float4*)anchors)[idx];
        const float4 D = ((const float4*)deltas)[(size_t)img * N_ANCH + idx];
        float w_  = __fadd_rn(__fsub_rn(A.z, A.x), 1.0f);
        float h_  = __fadd_rn(__fsub_rn(A.w, A.y), 1.0f);
        float cx = __fadd_rn(A.x, __fmul_rn(0.5f, w_));
        float cy = __fadd_rn(A.y, __fmul_rn(0.5f, h_));
        float dw = fminf(D.z, XFORM_CLIP);
        float dh = fminf(D.w, XFORM_CLIP);
        float pcx = __fadd_rn(__fmul_rn(D.x, w_), cx);
        float pcy = __fadd_rn(__fmul_rn(D.y, h_), cy);
        float pw  = __fmul_rn(__nv_expf(dw), w_);
        float ph  = __fmul_rn(__nv_expf(dh), h_);
        float hx = __fmul_rn(0.5f, pw), hy = __fmul_rn(0.5f, ph);
        float x1 = __fsub_rn(pcx, hx);
        float y1 = __fsub_rn(pcy, hy);
        float x2 = __fsub_rn(__fadd_rn(pcx, hx), 1.0f);
        float y2 = __fsub_rn(__fadd_rn(pcy, hy), 1.0f);
        x1 = fminf(fmaxf(x1, 0.0f), XMAX);
        x2 = fminf(fmaxf(x2, 0.0f), XMAX);
        y1 = fminf(fmaxf(y1, 0.0f), YMAX);
        y2 = fminf(fmaxf(y2, 0.0f), YMAX);
        float ww = __fadd_rn(__fsub_rn(x2, x1), 1.0f);
        float hh = __fadd_rn(__fsub_rn(y2, y1), 1.0f);
        g_props4[img * K_PRE + r2] = make_float4(x1, y1, x2, y2);
        g_area[img * K_PRE + r2] = __fmul_rn(ww, hh);
        g_valid[img * K_PRE + r2] = (ww >= 0.0f && hh >= 0.0f) ? 1 : 0;
        g_scores[img * K_PRE + r2] = score;
    }
    if (t == 0) g_state[img * 4 + 2] = 0u;
}

// ---------------- IoU test (div-free fast path, exact fallback) ----------------
__device__ __forceinline__ bool iou_sup(float4 a, float ai, float4 b, float aj) {
    float lx = fmaxf(a.x, b.x), ly = fmaxf(a.y, b.y);
    float rx = fminf(a.z, b.z), ry = fminf(a.w, b.w);
    float iw = fmaxf(__fadd_rn(__fsub_rn(rx, lx), 1.0f), 0.0f);
    float ih = fmaxf(__fadd_rn(__fsub_rn(ry, ly), 1.0f), 0.0f);
    float inter = __fmul_rn(iw, ih);
    float den = __fsub_rn(__fadd_rn(ai, aj), inter);
    float t = __fmaf_rn(-NMS_THRESH, den, inter);
    if (fabsf(t) <= __fmul_rn(1.2e-7f, den))
        return __fdiv_rn(inter, den) > NMS_THRESH;   // exact, rare
    return t > 0.0f;
}

// ---------------- fused mask + last-block greedy/pack ----------------
struct __align__(16) SMG {
    union {
        struct { float4 rbox[64]; float rar[64]; } m;
        struct { ull buf[2][2048]; ull skw[32]; } g;
    } u;
    int wsum[8];
    int stot;
    int done;
    unsigned int ticket;
};

__global__ void __launch_bounds__(256, 4) maskgreedy_kernel(float* __restrict__ out) {
    __shared__ SMG s;
    int img = blockIdx.y;
    int uu = blockIdx.x;                 // 0..527 upper-tri tiles
    int rb = 0, rem = uu;
    while (rem >= 32 - rb) { rem -= 32 - rb; rb++; }
    int cb = rb + rem;
    int t = threadIdx.x, wid = t >> 5, lane = t & 31;
    int r0 = rb * 64, j0 = cb * 64;
    if (t < 64) {
        int r = r0 + t;
        if (r < K_PRE) { s.u.m.rbox[t] = g_props4[img * K_PRE + r]; s.u.m.rar[t] = g_area[img * K_PRE + r]; }
        else           { s.u.m.rbox[t] = make_float4(1e9f, 1e9f, -1e9f, -1e9f); s.u.m.rar[t] = 1.0f; }
    }
    int jA = j0 + lane, jB = jA + 32;
    float4 bA = (jA < K_PRE) ? g_props4[img * K_PRE + jA] : make_float4(1e9f, 1e9f, -1e9f, -1e9f);
    float4 bB = (jB < K_PRE) ? g_props4[img * K_PRE + jB] : make_float4(1e9f, 1e9f, -1e9f, -1e9f);
    float aA = (jA < K_PRE) ? g_area[img * K_PRE + jA] : 1.0f;
    float aB = (jB < K_PRE) ? g_area[img * K_PRE + jB] : 1.0f;
    __syncthreads();
    bool diag = (cb == rb);
    // warp-per-row, rows from smem per iteration (measured-good form: issue 86%)
    for (int rr = wid; rr < 64; rr += 8) {
        int row = r0 + rr;
        float4 a = s.u.m.rbox[rr];
        float ai = s.u.m.rar[rr];
        bool sA = iou_sup(a, ai, bA, aA);
        bool sB = iou_sup(a, ai, bB, aB);
        if (diag) { sA = sA && (jA > row); sB = sB && (jB > row); }
        unsigned int lo = __ballot_sync(0xFFFFFFFFu, sA);
        unsigned int hi = __ballot_sync(0xFFFFFFFFu, sB);
        if (lane == 0)
            g_mask[((size_t)img * 2048 + row) * 32 + cb] = (ull)lo | ((ull)hi << 32);
    }
    // ---- ticket: last block of this image runs greedy + pack ----
    __threadfence();
    __syncthreads();
    if (t == 0) s.ticket = atomicAdd(&g_done3[img], 1u);
    __syncthreads();
    if (s.ticket != gridDim.x - 1) return;
    if (t == 0) g_done3[img] = 0u;

    const ull* M = &g_mask[(size_t)img * 2048 * 32];
    // chunk-0 load: register-batched __ldcg (MLP=8)
    if (t < 32) s.u.g.skw[t] = 0ull;
    {
        ull tmp0[8];
        #pragma unroll
        for (int u = 0; u < 8; u++) tmp0[u] = __ldcg(&M[t + u * 256]);
        #pragma unroll
        for (int u = 0; u < 8; u++) s.u.g.buf[0][t + u * 256] = tmp0[u];
    }
    if (t == 0) s.done = 0;
    __syncthreads();
    ull removed = 0ull;
    if (wid == 0) {
        const ull* v8 = (const ull*)(g_valid + img * K_PRE);
        #pragma unroll
        for (int w = 0; w < 8; w++) {
            int wi = lane * 8 + w;
            ull x = (wi < K_PRE / 8) ? v8[wi] : 0ull;
            #pragma unroll
            for (int b = 0; b < 8; b++)
                if (!((x >> (8 * b)) & 0xFFull)) removed |= 1ull << (w * 8 + b);
        }
    }
    int nk = 0;
    for (int c = 0; c < 32; c++) {
        int cbuf = c & 1, nbuf = cbuf ^ 1;
        if (wid > 0 && (c + 1) < 32) {
            // register-batched prefetch: issue all LDGs (MLP~10), then store
            const ull* src = &M[(size_t)(c + 1) * 2048];
            ull tmp[10];
            #pragma unroll
            for (int u = 0; u < 10; u++) {
                int i = (t - 32) + u * 224;
                tmp[u] = (i < 2048) ? __ldcg(&src[i]) : 0ull;
            }
            #pragma unroll
            for (int u = 0; u < 10; u++) {
                int i = (t - 32) + u * 224;
                if (i < 2048) s.u.g.buf[nbuf][i] = tmp[u];
            }
        }
        if (wid == 0) {
            ull cur = __shfl_sync(0xFFFFFFFFu, removed, c);
            int base = c * 64;
            int lim = K_PRE - base; if (lim > 64) lim = 64;
            if (lim < 64) cur |= (~0ull) << lim;   // kill out-of-range rows once
            ull kept = 0ull;
            // fully branchless row loop: serial chain = cur only (~16 cy/row)
            for (int qb = 0; qb < 64; qb += 8) {
                ull dw[8];
                #pragma unroll
                for (int r = 0; r < 8; r++)
                    dw[r] = s.u.g.buf[cbuf][(qb + r) * 32 + c];
                #pragma unroll
                for (int r = 0; r < 8; r++) {
                    int q = qb + r;
                    ull bit = 1ull << q;
                    ull rowword = s.u.g.buf[cbuf][q * 32 + lane];
                    bool keep = ((cur & bit) == 0ull);
                    ull km = keep ? ~0ull : 0ull;
                    kept |= bit & km;
                    removed |= rowword & km;
                    cur |= dw[r] & km;
                }
            }
            nk += __popcll(kept);
            if (lane == 0) {
                s.u.g.skw[c] = kept;
                if (nk >= K_POST) s.done = 1;
            }
        }
        __syncthreads();
        if (s.done) break;
    }
    // ---- fused stable-partition + pack (256 threads x 8 rows) ----
    unsigned int bits8 = (unsigned int)((s.u.g.skw[t >> 3] >> ((t & 7) * 8)) & 0xFFull);
    int sc = __popc(bits8);
    int v = sc;
    #pragma unroll
    for (int off = 1; off < 32; off <<= 1) {
        int n = __shfl_up_sync(0xFFFFFFFFu, v, off);
        if (lane >= off) v += n;
    }
    if (lane == 31) s.wsum[wid] = v;
    __syncthreads();
    if (wid == 0 && lane < 8) {
        int w = s.wsum[lane];
        #pragma unroll
        for (int off = 1; off < 8; off <<= 1) {
            int n = __shfl_up_sync(0xFFu, w, off);
            if ((int)lane >= off) w += n;
        }
        s.wsum[lane] = w;
        if (lane == 7) s.stot = w;
    }
    __syncthreads();
    int base8 = (wid > 0 ? s.wsum[wid - 1] : 0) + (v - sc);
    int total = s.stot;
    #pragma unroll
    for (int qq = 0; qq < 8; qq++) {
        int rr = t * 8 + qq;
        if (rr >= K_PRE) break;
        int flag = (int)((bits8 >> qq) & 1u);
        int kb = base8 + __popc(bits8 & ((1u << qq) - 1u));
        int p = flag ? kb : total + (rr - kb);
        if (p < K_POST) {
            float4 P = g_props4[img * K_PRE + rr];
            float* o = &out[((size_t)img * K_POST + p) * 5];
            o[0] = P.x; o[1] = P.y; o[2] = P.z; o[3] = P.w;
            o[4] = flag ? g_scores[img * K_PRE + rr] : NEG_BIG;
        }
    }
}

// ---------------- launch ----------------
extern "C" void kernel_launch(void* const* d_in, const int* in_sizes, int n_in,
                              void* d_out, int out_size) {
    const float *anchors = nullptr, *obj = nullptr, *deltas = nullptr;
    for (int i = 0; i < n_in; i++) {
        if (in_sizes[i] == N_ANCH * 4)              anchors = (const float*)d_in[i];
        else if (in_sizes[i] == N_IMG * N_ANCH)     obj     = (const float*)d_in[i];
        else if (in_sizes[i] == N_IMG * N_ANCH * 4) deltas  = (const float*)d_in[i];
    }
    float* out = (float*)d_out;

    hist_kernel<<<dim3(31, N_IMG), 256>>>((const float4*)obj);
    compact_kernel<<<dim3(31, N_IMG), 256>>>((const float4*)obj);
    sortdec_kernel<<<N_IMG, 1024>>>(anchors, deltas);
    maskgreedy_kernel<<<dim3(528, N_IMG), 256>>>(out);
    (void)out_size;
}

// round 15
// speedup vs baseline: 1.3881x; 1.0346x over previous
#include <cuda_runtime.h>
#include <cstdint>

// libdevice precise expf (what XLA lowers jnp.exp(f32) to), immune to fast-math.
extern "C" __device__ float __nv_expf(float);

typedef unsigned long long ull;

// ---------------- problem constants ----------------
#define N_IMG 8
#define N_ANCH 250000
#define N_ANCH4 62500
#define K_PRE 2000
#define K_POST 1000
#define CAND_CAP 4096
#define NMS_THRESH 0.7f
#define XFORM_CLIP 4.135166556742356f
#define XMAX 1332.0f
#define YMAX 799.0f
#define NEG_BIG -1e9f
#define NBINS 4096
#define NB2 1024            // refined bins (512 in-bin + overflow)

// ---------------- device scratch (zero-init at load; self-cleaning per replay) ----------------
__device__ unsigned int g_hist[N_IMG * NBINS];
__device__ unsigned int g_hist2[N_IMG * NB2];
__device__ unsigned int g_done[N_IMG];
__device__ unsigned int g_done3[N_IMG];
__device__ unsigned int g_state[N_IMG * 4];      // [0]=coarse threshold key, [2]=cand_cnt
__device__ ull    g_cand[N_IMG * CAND_CAP];
__device__ float4 g_props4[N_IMG * K_PRE];
__device__ float  g_area[N_IMG * K_PRE];
__device__ float  g_scores[N_IMG * K_PRE];
__device__ unsigned char g_valid[N_IMG * K_PRE];
__device__ ull    g_mask[N_IMG * 2048 * 32];

__device__ __forceinline__ unsigned int okey_of(float f) {
    unsigned int b = __float_as_uint(f);
    return b ^ ((b & 0x80000000u) ? 0xFFFFFFFFu : 0x80000000u);
}

// ---------------- histogram (12-bit bins) + fused last-block threshold scan ----------------
__global__ void hist_kernel(const float4* __restrict__ obj4) {
    int img = blockIdx.y, t = threadIdx.x;
    __shared__ unsigned int sh[2][NBINS];
    __shared__ unsigned int s_ticket;
    __shared__ unsigned int wsums[8];
    for (int i = t; i < 2 * NBINS; i += 256) ((unsigned int*)sh)[i] = 0u;
    __syncthreads();
    const float4* o = obj4 + (size_t)img * N_ANCH4;
    int base = blockIdx.x * 2048 + t;
    float4 v[8]; bool m[8];
    #pragma unroll
    for (int u = 0; u < 8; u++) {
        int i = base + u * 256;
        m[u] = (i < N_ANCH4);
        v[u] = m[u] ? o[i] : make_float4(0.f, 0.f, 0.f, 0.f);
    }
    int p = (t >> 5) & 1;
    #pragma unroll
    for (int u = 0; u < 8; u++) if (m[u]) {
        atomicAdd(&sh[p][okey_of(v[u].x) >> 20], 1u);
        atomicAdd(&sh[p][okey_of(v[u].y) >> 20], 1u);
        atomicAdd(&sh[p][okey_of(v[u].z) >> 20], 1u);
        atomicAdd(&sh[p][okey_of(v[u].w) >> 20], 1u);
    }
    __syncthreads();
    for (int i = t; i < NBINS; i += 256) {
        unsigned int s = sh[0][i] + sh[1][i];
        if (s) atomicAdd(&g_hist[img * NBINS + i], s);
    }
    // ---- last-block coarse threshold scan (fence + ticket) ----
    __threadfence();
    __syncthreads();
    if (t == 0) s_ticket = atomicAdd(&g_done[img], 1u);
    __syncthreads();
    if (s_ticket == gridDim.x - 1) {
        int lane = t & 31, wid = t >> 5;
        int r0 = t * 16;                     // descending positions; bin = 4095 - r
        unsigned int cc[16], s[16];
        #pragma unroll
        for (int u = 0; u < 16; u++)
            cc[u] = __ldcg(&g_hist[img * NBINS + (NBINS - 1 - (r0 + u))]);
        unsigned int run = 0;
        #pragma unroll
        for (int u = 0; u < 16; u++) { run += cc[u]; s[u] = run; }
        unsigned int vv = run;
        #pragma unroll
        for (int off = 1; off < 32; off <<= 1) {
            unsigned int n = __shfl_up_sync(0xFFFFFFFFu, vv, off);
            if (lane >= off) vv += n;
        }
        if (lane == 31) wsums[wid] = vv;
        __syncthreads();
        if (wid == 0 && lane < 8) {
            unsigned int w = wsums[lane];
            #pragma unroll
            for (int off = 1; off < 8; off <<= 1) {
                unsigned int n = __shfl_up_sync(0xFFu, w, off);
                if ((int)lane >= off) w += n;
            }
            wsums[lane] = w;
        }
        __syncthreads();
        unsigned int excl = (wid > 0 ? wsums[wid - 1] : 0u) + (vv - run);
        if (excl < K_PRE && excl + run >= K_PRE) {
            int u = 0;
            #pragma unroll
            for (int q = 15; q >= 0; q--) if (excl + s[q] >= K_PRE) u = q;
            g_state[img * 4 + 0] = (unsigned int)(NBINS - 1 - (r0 + u)) << 20;
        }
        #pragma unroll
        for (int u = 0; u < 16; u++)
            g_hist[img * NBINS + (NBINS - 1 - (r0 + u))] = 0u;
        if (t == 0) g_done[img] = 0u;
    }
}

// ---------------- compact candidates + refined 21-bit histogram ----------------
__global__ void compact_kernel(const float4* __restrict__ obj4) {
    int img = blockIdx.y, t = threadIdx.x;
    __shared__ unsigned int h2[NB2];
    #pragma unroll
    for (int u = 0; u < 4; u++) h2[t + u * 256] = 0u;
    __syncthreads();
    unsigned int T = g_state[img * 4 + 0];
    unsigned int T11 = T >> 11;
    const float4* o = obj4 + (size_t)img * N_ANCH4;
    int base = blockIdx.x * 2048 + t;
    float4 v[8]; bool m[8];
    #pragma unroll
    for (int u = 0; u < 8; u++) {
        int i = base + u * 256;
        m[u] = (i < N_ANCH4);
        v[u] = m[u] ? o[i] : make_float4(0.f, 0.f, 0.f, 0.f);
    }
    #pragma unroll
    for (int u = 0; u < 8; u++) if (m[u]) {
        int i = base + u * 256;
        #pragma unroll
        for (int c = 0; c < 4; c++) {
            float f = (c == 0) ? v[u].x : (c == 1) ? v[u].y : (c == 2) ? v[u].z : v[u].w;
            unsigned int k = okey_of(f);
            if (k >= T) {
                unsigned int d = (k >> 11) - T11; if (d > NB2 - 1) d = NB2 - 1;
                atomicAdd(&h2[d], 1u);
                unsigned int pos = atomicAdd(&g_state[img * 4 + 2], 1u);
                if (pos < CAND_CAP)
                    g_cand[img * CAND_CAP + pos] =
                        ((ull)k << 32) | (unsigned int)(~(unsigned int)(4 * i + c));
            }
        }
    }
    __syncthreads();
    #pragma unroll
    for (int u = 0; u < 4; u++) {
        unsigned int s = h2[t + u * 256];
        if (s) atomicAdd(&g_hist2[img * NB2 + t + u * 256], s);
    }
}

// ---------------- sortdec: refined select + V=2 bitonic + decode ----------------
__device__ __forceinline__ void cas_reg(ull& a, ull& b, bool desc) {
    if ((a < b) == desc) { ull tmp = a; a = b; b = tmp; }
}

__global__ void sortdec_kernel(const float* __restrict__ anchors,
                               const float* __restrict__ deltas) {
    int img = blockIdx.x, t = threadIdx.x;   // 1024 threads
    __shared__ ull sh[CAND_CAP];             // 32 KB
    __shared__ unsigned int wsums[32];
    __shared__ int sT2;
    __shared__ int c2cnt;
    int w = t >> 5, lane = t & 31;
    unsigned int cnt = g_state[img * 4 + 2];
    if (cnt > CAND_CAP) cnt = CAND_CAP;
    if (t == 0) c2cnt = 0;
    ull v[4];
    #pragma unroll
    for (int u = 0; u < 4; u++) {
        int i = t + u * 1024;
        v[u] = (i < (int)cnt) ? g_cand[img * CAND_CAP + i] : 0ull;
    }
    unsigned int c = __ldcg(&g_hist2[img * NB2 + (NB2 - 1 - t)]);
    g_hist2[img * NB2 + (NB2 - 1 - t)] = 0u;   // self-clean for next replay
    unsigned int vv = c;
    #pragma unroll
    for (int off = 1; off < 32; off <<= 1) {
        unsigned int n = __shfl_up_sync(0xFFFFFFFFu, vv, off);
        if (lane >= off) vv += n;
    }
    if (lane == 31) wsums[w] = vv;
    __syncthreads();
    if (w == 0) {
        unsigned int x = wsums[lane];
        #pragma unroll
        for (int off = 1; off < 32; off <<= 1) {
            unsigned int n = __shfl_up_sync(0xFFFFFFFFu, x, off);
            if (lane >= off) x += n;
        }
        wsums[lane] = x;
    }
    __syncthreads();
    unsigned int excl = (w > 0 ? wsums[w - 1] : 0u) + (vv - c);
    if (excl < K_PRE && excl + c >= K_PRE) sT2 = NB2 - 1 - t;
    __syncthreads();
    unsigned int T11 = g_state[img * 4 + 0] >> 11;
    unsigned int dstar = (unsigned int)sT2;
    #pragma unroll
    for (int u = 0; u < 4; u++) {
        int i = t + u * 1024;
        unsigned int k = (unsigned int)(v[u] >> 32);
        unsigned int d = (k >> 11) - T11; if (d > NB2 - 1) d = NB2 - 1;
        bool p = (i < (int)cnt) && (d >= dstar);
        unsigned int ball = __ballot_sync(0xFFFFFFFFu, p);
        int bpos = 0;
        if (lane == 0 && ball) bpos = atomicAdd(&c2cnt, __popc(ball));
        bpos = __shfl_sync(0xFFFFFFFFu, bpos, 0);
        if (p) sh[bpos + __popc(ball & ((1u << lane) - 1u))] = v[u];
    }
    __syncthreads();
    int C2 = c2cnt;
    if (C2 <= 2048) {
        for (int i = t; i < 2048; i += 1024) if (i >= C2) sh[i] = 0ull;
        __syncthreads();
        ull r[2];
        #pragma unroll
        for (int e = 0; e < 2; e++) r[e] = sh[(w << 6) | (e << 5) | lane];
        for (int k = 2; k <= 2048; k <<= 1) {
            if (k >= 128) {
                #pragma unroll
                for (int e = 0; e < 2; e++) sh[(w << 6) | (e << 5) | lane] = r[e];
                __syncthreads();
                for (int j = k >> 1; j >= 64; j >>= 1) {
                    int i = ((t & ~(j - 1)) << 1) | (t & (j - 1));
                    int ixj = i | j;
                    bool desc = ((i & k) == 0);
                    ull A = sh[i], B = sh[ixj];
                    if ((A < B) == desc) { sh[i] = B; sh[ixj] = A; }
                    __syncthreads();
                }
                #pragma unroll
                for (int e = 0; e < 2; e++) r[e] = sh[(w << 6) | (e << 5) | lane];
            }
            if (k >= 64) {
                bool d = (((w << 6) & k) == 0);
                cas_reg(r[0], r[1], d);
            }
            int jmax = (k >> 1) < 16 ? (k >> 1) : 16;
            for (int j = jmax; j >= 1; j >>= 1) {
                #pragma unroll
                for (int e = 0; e < 2; e++) {
                    int i = (w << 6) | (e << 5) | lane;
                    bool desc = ((i & k) == 0);
                    bool iLow = ((lane & j) == 0);
                    ull p2 = __shfl_xor_sync(0xFFFFFFFFu, r[e], j);
                    ull mx = (r[e] > p2) ? r[e] : p2;
                    ull mn = (r[e] > p2) ? p2 : r[e];
                    r[e] = (iLow == desc) ? mx : mn;
                }
            }
        }
        #pragma unroll
        for (int e = 0; e < 2; e++) sh[(w << 6) | (e << 5) | lane] = r[e];
        __syncthreads();
    } else {
        for (int i = t; i < CAND_CAP; i += 1024)
            sh[i] = (i < (int)cnt) ? g_cand[img * CAND_CAP + i] : 0ull;
        __syncthreads();
        for (int k = 2; k <= CAND_CAP; k <<= 1) {
            for (int j = k >> 1; j > 0; j >>= 1) {
                for (int i = t; i < CAND_CAP; i += 1024) {
                    int ixj = i ^ j;
                    if (ixj > i) {
                        bool desc = ((i & k) == 0);
                        ull A = sh[i], B = sh[ixj];
                        if (desc ? (A < B) : (A > B)) { sh[i] = B; sh[ixj] = A; }
                    }
                }
                __syncthreads();
            }
        }
    }
    for (int r2 = t; r2 < K_PRE; r2 += 1024) {
        ull e = sh[r2];
        int idx = (int)(~(unsigned int)(e & 0xFFFFFFFFull));
        unsigned int kk = (unsigned int)(e >> 32);
        float score = __uint_as_float((kk & 0x80000000u) ? (kk ^ 0x80000000u) : ~kk);
        const float4 A = ((const float4*)anchors)[idx];
        const float4 D = ((const float4*)deltas)[(size_t)img * N_ANCH + idx];
        float w_  = __fadd_rn(__fsub_rn(A.z, A.x), 1.0f);
        float h_  = __fadd_rn(__fsub_rn(A.w, A.y), 1.0f);
        float cx = __fadd_rn(A.x, __fmul_rn(0.5f, w_));
        float cy = __fadd_rn(A.y, __fmul_rn(0.5f, h_));
        float dw = fminf(D.z, XFORM_CLIP);
        float dh = fminf(D.w, XFORM_CLIP);
        float pcx = __fadd_rn(__fmul_rn(D.x, w_), cx);
        float pcy = __fadd_rn(__fmul_rn(D.y, h_), cy);
        float pw  = __fmul_rn(__nv_expf(dw), w_);
        float ph  = __fmul_rn(__nv_expf(dh), h_);
        float hx = __fmul_rn(0.5f, pw), hy = __fmul_rn(0.5f, ph);
        float x1 = __fsub_rn(pcx, hx);
        float y1 = __fsub_rn(pcy, hy);
        float x2 = __fsub_rn(__fadd_rn(pcx, hx), 1.0f);
        float y2 = __fsub_rn(__fadd_rn(pcy, hy), 1.0f);
        x1 = fminf(fmaxf(x1, 0.0f), XMAX);
        x2 = fminf(fmaxf(x2, 0.0f), XMAX);
        y1 = fminf(fmaxf(y1, 0.0f), YMAX);
        y2 = fminf(fmaxf(y2, 0.0f), YMAX);
        float ww = __fadd_rn(__fsub_rn(x2, x1), 1.0f);
        float hh = __fadd_rn(__fsub_rn(y2, y1), 1.0f);
        g_props4[img * K_PRE + r2] = make_float4(x1, y1, x2, y2);
        g_area[img * K_PRE + r2] = __fmul_rn(ww, hh);
        g_valid[img * K_PRE + r2] = (ww >= 0.0f && hh >= 0.0f) ? 1 : 0;
        g_scores[img * K_PRE + r2] = score;
    }
    if (t == 0) g_state[img * 4 + 2] = 0u;
}

// ---------------- IoU test (div-free fast path, exact fallback) ----------------
__device__ __forceinline__ bool iou_sup(float4 a, float ai, float4 b, float aj) {
    float lx = fmaxf(a.x, b.x), ly = fmaxf(a.y, b.y);
    float rx = fminf(a.z, b.z), ry = fminf(a.w, b.w);
    float iw = fmaxf(__fadd_rn(__fsub_rn(rx, lx), 1.0f), 0.0f);
    float ih = fmaxf(__fadd_rn(__fsub_rn(ry, ly), 1.0f), 0.0f);
    float inter = __fmul_rn(iw, ih);
    float den = __fsub_rn(__fadd_rn(ai, aj), inter);
    float t = __fmaf_rn(-NMS_THRESH, den, inter);
    if (fabsf(t) <= __fmul_rn(1.2e-7f, den))
        return __fdiv_rn(inter, den) > NMS_THRESH;   // exact, rare
    return t > 0.0f;
}

// ---------------- fused mask + last-block greedy/pack ----------------
struct __align__(16) SMG {
    union {
        struct { float4 rbox[64]; float rar[64]; } m;
        struct { ull buf[2][2048]; ull skw[32]; } g;
    } u;
    int wsum[8];
    int stot;
    int done;
    unsigned int ticket;
};

__global__ void __launch_bounds__(256, 4) maskgreedy_kernel(float* __restrict__ out) {
    __shared__ SMG s;
    int img = blockIdx.y;
    int uu = blockIdx.x;                 // 0..527 upper-tri tiles
    int rb = 0, rem = uu;
    while (rem >= 32 - rb) { rem -= 32 - rb; rb++; }
    int cb = rb + rem;
    int t = threadIdx.x, wid = t >> 5, lane = t & 31;
    int r0 = rb * 64, j0 = cb * 64;
    if (t < 64) {
        int r = r0 + t;
        if (r < K_PRE) { s.u.m.rbox[t] = g_props4[img * K_PRE + r]; s.u.m.rar[t] = g_area[img * K_PRE + r]; }
        else           { s.u.m.rbox[t] = make_float4(1e9f, 1e9f, -1e9f, -1e9f); s.u.m.rar[t] = 1.0f; }
    }
    int jA = j0 + lane, jB = jA + 32;
    float4 bA = (jA < K_PRE) ? g_props4[img * K_PRE + jA] : make_float4(1e9f, 1e9f, -1e9f, -1e9f);
    float4 bB = (jB < K_PRE) ? g_props4[img * K_PRE + jB] : make_float4(1e9f, 1e9f, -1e9f, -1e9f);
    float aA = (jA < K_PRE) ? g_area[img * K_PRE + jA] : 1.0f;
    float aB = (jB < K_PRE) ? g_area[img * K_PRE + jB] : 1.0f;
    __syncthreads();
    bool diag = (cb == rb);
    // warp-per-row, rows from smem per iteration (measured-good form: issue 86%)
    for (int rr = wid; rr < 64; rr += 8) {
        int row = r0 + rr;
        float4 a = s.u.m.rbox[rr];
        float ai = s.u.m.rar[rr];
        bool sA = iou_sup(a, ai, bA, aA);
        bool sB = iou_sup(a, ai, bB, aB);
        if (diag) { sA = sA && (jA > row); sB = sB && (jB > row); }
        unsigned int lo = __ballot_sync(0xFFFFFFFFu, sA);
        unsigned int hi = __ballot_sync(0xFFFFFFFFu, sB);
        if (lane == 0)
            g_mask[((size_t)img * 2048 + row) * 32 + cb] = (ull)lo | ((ull)hi << 32);
    }
    // ---- ticket: last block of this image runs greedy + pack ----
    __threadfence();
    __syncthreads();
    if (t == 0) s.ticket = atomicAdd(&g_done3[img], 1u);
    __syncthreads();
    if (s.ticket != gridDim.x - 1) return;
    if (t == 0) g_done3[img] = 0u;

    const ull* M = &g_mask[(size_t)img * 2048 * 32];
    // chunk-0 load: register-batched __ldcg (MLP=8)
    if (t < 32) s.u.g.skw[t] = 0ull;
    {
        ull tmp0[8];
        #pragma unroll
        for (int u = 0; u < 8; u++) tmp0[u] = __ldcg(&M[t + u * 256]);
        #pragma unroll
        for (int u = 0; u < 8; u++) s.u.g.buf[0][t + u * 256] = tmp0[u];
    }
    if (t == 0) s.done = 0;
    __syncthreads();
    ull removed = 0ull;
    if (wid == 0) {
        const ull* v8 = (const ull*)(g_valid + img * K_PRE);
        #pragma unroll
        for (int w = 0; w < 8; w++) {
            int wi = lane * 8 + w;
            ull x = (wi < K_PRE / 8) ? v8[wi] : 0ull;
            #pragma unroll
            for (int b = 0; b < 8; b++)
                if (!((x >> (8 * b)) & 0xFFull)) removed |= 1ull << (w * 8 + b);
        }
    }
    int nk = 0;
    for (int c = 0; c < 32; c++) {
        int cbuf = c & 1, nbuf = cbuf ^ 1;
        if (wid > 0 && (c + 1) < 32) {
            // register-batched prefetch: issue all LDGs (MLP~10), then store
            const ull* src = &M[(size_t)(c + 1) * 2048];
            ull tmp[10];
            #pragma unroll
            for (int u = 0; u < 10; u++) {
                int i = (t - 32) + u * 224;
                tmp[u] = (i < 2048) ? __ldcg(&src[i]) : 0ull;
            }
            #pragma unroll
            for (int u = 0; u < 10; u++) {
                int i = (t - 32) + u * 224;
                if (i < 2048) s.u.g.buf[nbuf][i] = tmp[u];
            }
        }
        if (wid == 0) {
            ull cur = __shfl_sync(0xFFFFFFFFu, removed, c);
            int base = c * 64;
            int lim = K_PRE - base; if (lim > 64) lim = 64;
            if (lim < 64) cur |= (~0ull) << lim;   // kill out-of-range rows once
            ull kept = 0ull;
            // fully branchless row loop; rw/dw preloaded so chain is pure ALU
            for (int qb = 0; qb < 64; qb += 8) {
                ull rw[8], dw[8];
                #pragma unroll
                for (int r = 0; r < 8; r++) {
                    rw[r] = s.u.g.buf[cbuf][(qb + r) * 32 + lane];
                    dw[r] = s.u.g.buf[cbuf][(qb + r) * 32 + c];
                }
                #pragma unroll
                for (int r = 0; r < 8; r++) {
                    int q = qb + r;
                    ull bit = 1ull << q;
                    bool keep = ((cur & bit) == 0ull);
                    ull km = keep ? ~0ull : 0ull;
                    kept |= bit & km;
                    removed |= rw[r] & km;
                    cur |= dw[r] & km;
                }
            }
            nk += __popcll(kept);
            if (lane == 0) {
                s.u.g.skw[c] = kept;
                if (nk >= K_POST) s.done = 1;
            }
        }
        __syncthreads();
        if (s.done) break;
    }
    // ---- fused stable-partition + pack (256 threads x 8 rows) ----
    unsigned int bits8 = (unsigned int)((s.u.g.skw[t >> 3] >> ((t & 7) * 8)) & 0xFFull);
    int sc = __popc(bits8);
    int v = sc;
    #pragma unroll
    for (int off = 1; off < 32; off <<= 1) {
        int n = __shfl_up_sync(0xFFFFFFFFu, v, off);
        if (lane >= off) v += n;
    }
    if (lane == 31) s.wsum[wid] = v;
    __syncthreads();
    if (wid == 0 && lane < 8) {
        int w = s.wsum[lane];
        #pragma unroll
        for (int off = 1; off < 8; off <<= 1) {
            int n = __shfl_up_sync(0xFFu, w, off);
            if ((int)lane >= off) w += n;
        }
        s.wsum[lane] = w;
        if (lane == 7) s.stot = w;
    }
    __syncthreads();
    int base8 = (wid > 0 ? s.wsum[wid - 1] : 0) + (v - sc);
    int total = s.stot;
    #pragma unroll
    for (int qq = 0; qq < 8; qq++) {
        int rr = t * 8 + qq;
        if (rr >= K_PRE) break;
        int flag = (int)((bits8 >> qq) & 1u);
        int kb = base8 + __popc(bits8 & ((1u << qq) - 1u));
        int p = flag ? kb : total + (rr - kb);
        if (p < K_POST) {
            float4 P = g_props4[img * K_PRE + rr];
            float* o = &out[((size_t)img * K_POST + p) * 5];
            o[0] = P.x; o[1] = P.y; o[2] = P.z; o[3] = P.w;
            o[4] = flag ? g_scores[img * K_PRE + rr] : NEG_BIG;
        }
    }
}

// ---------------- launch ----------------
extern "C" void kernel_launch(void* const* d_in, const int* in_sizes, int n_in,
                              void* d_out, int out_size) {
    const float *anchors = nullptr, *obj = nullptr, *deltas = nullptr;
    for (int i = 0; i < n_in; i++) {
        if (in_sizes[i] == N_ANCH * 4)              anchors = (const float*)d_in[i];
        else if (in_sizes[i] == N_IMG * N_ANCH)     obj     = (const float*)d_in[i];
        else if (in_sizes[i] == N_IMG * N_ANCH * 4) deltas  = (const float*)d_in[i];
    }
    float* out = (float*)d_out;

    hist_kernel<<<dim3(31, N_IMG), 256>>>((const float4*)obj);
    compact_kernel<<<dim3(31, N_IMG), 256>>>((const float4*)obj);
    sortdec_kernel<<<N_IMG, 1024>>>(anchors, deltas);
    maskgreedy_kernel<<<dim3(528, N_IMG), 256>>>(out);
    (void)out_size;
}